// round 10
// baseline (speedup 1.0000x reference)
#include <cuda_runtime.h>

#define TILE_X 32
#define TILE_Y 64
#define HALO  5
#define NRY   74              // halo rows (TILE_Y + 2*HALO)
#define HSTRIDE 33            // hA row stride in ulonglong2 (pad: kills STS conflicts)
#define NITEMS  608           // 76 virtual rows x 8 q (r<74 guarded)
#define IMG   512
#define BATCH 32
#define NBLK  (16*8*32)       // 4096 blocks

typedef unsigned long long u64;

__device__ double       g_accum;   // zero at module load; reset by last block
__device__ unsigned int g_count;

// Gaussian window (ws=11, sigma=1.5), normalized — matches jnp float32 chain
__device__ __forceinline__ float gw(int k) {
    const float G[11] = {0.00102838f, 0.00759876f, 0.03600077f, 0.10936069f,
                         0.21300554f, 0.26601173f, 0.21300554f, 0.10936069f,
                         0.03600077f, 0.00759876f, 0.00102838f};
    return G[k];
}

// ---- f32x2 helpers: register-pair views, NO integer shifts ----
__device__ __forceinline__ u64 pk2(float lo, float hi) {
    u64 d; asm("mov.b64 %0, {%1, %2};" : "=l"(d) : "f"(lo), "f"(hi));
    return d;
}
__device__ __forceinline__ void upk2(u64 v, float& lo, float& hi) {
    asm("mov.b64 {%0, %1}, %2;" : "=f"(lo), "=f"(hi) : "l"(v));
}
__device__ __forceinline__ u64 fma2(u64 a, u64 b, u64 c) {
    u64 d; asm("fma.rn.f32x2 %0, %1, %2, %3;" : "=l"(d) : "l"(a), "l"(b), "l"(c));
    return d;
}
__device__ __forceinline__ u64 mul2(u64 a, u64 b) {
    u64 d; asm("mul.rn.f32x2 %0, %1, %2;" : "=l"(d) : "l"(a), "l"(b));
    return d;
}

// accumulate window element k (0..13) into the 4 packed h-accumulators
__device__ __forceinline__ void acc_tap(int k, float pv, float tv,
                                        u64* sm, u64* se) {
    float s = pv + tv;
    float d = pv - tv;
    u64 wk = pk2(s, d);
    u64 sq = mul2(wk, wk);                       // (s^2, d^2)
    #pragma unroll
    for (int i = 0; i < 4; i++) {
        int kk = k - i;
        if (kk >= 0 && kk < 11) {
            float g = gw(kk);
            u64 g2 = pk2(g, g);                  // compile-time constant pair
            sm[i] = fma2(g2, wk, sm[i]);
            se[i] = fma2(g2, sq, se[i]);
        }
    }
}

__global__ __launch_bounds__(256, 5)
void ssim_main_kernel(const float* __restrict__ pred,
                      const float* __restrict__ targ,
                      float* __restrict__ out)
{
    // packed horizontal blurs: ( (mu_s,mu_d) , (E_ss,E_dd) ), stride-33 rows
    __shared__ __align__(16) ulonglong2 hA[NRY * HSTRIDE];      // 38.2 KB
    __shared__ float red[8];

    const int tid = threadIdx.x;                 // 0..255
    const int n  = blockIdx.z;
    const int x0 = blockIdx.x * TILE_X - HALO;
    const int y0 = blockIdx.y * TILE_Y - HALO;
    const float* __restrict__ pbase = pred + (size_t)n * IMG * IMG;
    const float* __restrict__ tbase = targ + (size_t)n * IMG * IMG;
    const bool xint = (blockIdx.x > 0) && (blockIdx.x < (IMG / TILE_X - 1));

    // ---- Phase 1+2 fused: horizontal blur of (s,d),(s^2,d^2) from gmem.
    // Item remap for conflict-free STS: q=(it>>2)&7, r=4*(it>>5)+(it&3).
    // An 8-lane store phase covers 4 rows x 2 q -> 8 distinct bank groups.
    for (int it = tid; it < NITEMS; it += 256) {
        int q = (it >> 2) & 7;
        int r = ((it >> 5) << 2) | (it & 3);
        if (r >= NRY) continue;
        int gy = y0 + r;
        bool yin = (unsigned)gy < IMG;

        u64 sm[4] = {0ull, 0ull, 0ull, 0ull};    // (mu_s_h, mu_d_h)
        u64 se[4] = {0ull, 0ull, 0ull, 0ull};    // (E_ss_h, E_dd_h)

        if (yin) {
            const float* __restrict__ prow = pbase + (size_t)gy * IMG;
            const float* __restrict__ trow = tbase + (size_t)gy * IMG;
            int a0 = x0 + 4 * q - 3;             // a0+4 is 16B-aligned
            if (xint) {
                // tap 0 scalar
                float p3 = __ldg(prow + a0 + 3);
                float t3 = __ldg(trow + a0 + 3);
                // taps 1..4
                float4 a = __ldg((const float4*)(prow + a0 + 4));
                float4 b = __ldg((const float4*)(trow + a0 + 4));
                acc_tap(0, p3, t3, sm, se);
                acc_tap(1, a.x, b.x, sm, se);
                acc_tap(2, a.y, b.y, sm, se);
                acc_tap(3, a.z, b.z, sm, se);
                acc_tap(4, a.w, b.w, sm, se);
                // taps 5..8
                a = __ldg((const float4*)(prow + a0 + 8));
                b = __ldg((const float4*)(trow + a0 + 8));
                acc_tap(5, a.x, b.x, sm, se);
                acc_tap(6, a.y, b.y, sm, se);
                acc_tap(7, a.z, b.z, sm, se);
                acc_tap(8, a.w, b.w, sm, se);
                // taps 9..12
                a = __ldg((const float4*)(prow + a0 + 12));
                b = __ldg((const float4*)(trow + a0 + 12));
                // tap 13 scalar
                float p16 = __ldg(prow + a0 + 16);
                float t16 = __ldg(trow + a0 + 16);
                acc_tap(9,  a.x, b.x, sm, se);
                acc_tap(10, a.y, b.y, sm, se);
                acc_tap(11, a.z, b.z, sm, se);
                acc_tap(12, a.w, b.w, sm, se);
                acc_tap(13, p16, t16, sm, se);
            } else {
                #pragma unroll
                for (int k = 0; k < 14; k++) {
                    int gx = a0 + k + 3;         // = x0 + 4q + k
                    bool in = (unsigned)gx < IMG;
                    float pv = in ? __ldg(prow + gx) : 0.f;
                    float tv = in ? __ldg(trow + gx) : 0.f;
                    acc_tap(k, pv, tv, sm, se);
                }
            }
        }

        int ho = r * HSTRIDE + q * 4;
        #pragma unroll
        for (int i = 0; i < 4; i++)
            hA[ho + i] = make_ulonglong2(sm[i], se[i]);   // STS.128, conflict-free
    }
    __syncthreads();

    // ---- Phase 3: vertical blur + SSIM, 8 consecutive rows per thread
    const int tx = tid & 31;
    const int ty = tid >> 5;                     // 0..7
    const int rbase = ty * 8;                    // output rows rbase..rbase+7

    u64 m[8], e[8];                              // (mu_s, mu_d), (E_ss, E_dd)
    #pragma unroll
    for (int i = 0; i < 8; i++) { m[i] = 0ull; e[i] = 0ull; }

    #pragma unroll
    for (int j = 0; j < 18; j++) {
        ulonglong2 v = hA[(rbase + j) * HSTRIDE + tx];   // LDS.128, conflict-free
        #pragma unroll
        for (int i = 0; i < 8; i++) {
            int k = j - i;
            if (k >= 0 && k < 11) {
                float g = gw(k);
                u64 g2 = pk2(g, g);
                m[i] = fma2(g2, v.x, m[i]);
                e[i] = fma2(g2, v.y, e[i]);
            }
        }
    }

    float acc = 0.f;
    #pragma unroll
    for (int i = 0; i < 8; i++) {
        u64 msq = mul2(m[i], m[i]);              // (mu_s^2, mu_d^2)
        float ms2, md2, Ess, Edd;
        upk2(msq, ms2, md2);
        upk2(e[i], Ess, Edd);
        // 2*mu1mu2    = (ms2-md2)/2   mu1^2+mu2^2 = (ms2+md2)/2
        // 2*sigma12   = (Ess-Edd)/2 - 2mu1mu2
        // v1+v2       = (Ess+Edd)/2 - (mu1^2+mu2^2)
        const float C1 = 1e-4f;                  // 0.01^2
        const float C2 = 9e-4f;                  // 0.03^2
        float B = 0.5f * (ms2 - md2);
        float A = 0.5f * (ms2 + md2);
        float num = (B + C1) * (0.5f * (Ess - Edd) - B + C2);
        float den = (A + C1) * (0.5f * (Ess + Edd) - A + C2);
        acc += __fdividef(num, den);
    }

    // ---- Phase 4: block reduce, last-block finalize (single kernel)
    #pragma unroll
    for (int o = 16; o > 0; o >>= 1)
        acc += __shfl_xor_sync(0xffffffffu, acc, o);
    if ((tid & 31) == 0) red[tid >> 5] = acc;
    __syncthreads();
    if (tid == 0) {
        float v = red[0] + red[1] + red[2] + red[3] +
                  red[4] + red[5] + red[6] + red[7];
        atomicAdd(&g_accum, (double)v);
        __threadfence();
        unsigned old = atomicAdd(&g_count, 1u);
        if (old == NBLK - 1) {
            __threadfence();
            double s = *((volatile double*)&g_accum);
            out[0] = (float)(1.0 - s / ((double)BATCH * IMG * IMG));
            g_accum = 0.0;                       // reset for next graph replay
            g_count = 0u;
        }
    }
}

extern "C" void kernel_launch(void* const* d_in, const int* in_sizes, int n_in,
                              void* d_out, int out_size)
{
    const float* pred = (const float*)d_in[0];
    const float* targ = (const float*)d_in[1];
    float* out = (float*)d_out;

    dim3 grid(IMG / TILE_X, IMG / TILE_Y, BATCH);    // 16 x 8 x 32
    ssim_main_kernel<<<grid, 256>>>(pred, targ, out);
}

// round 11
// speedup vs baseline: 1.0360x; 1.0360x over previous
#include <cuda_runtime.h>

#define TILE_X 32
#define TILE_Y 64
#define HALO  5
#define NRY   74              // halo rows (TILE_Y + 2*HALO)
#define IMG   512
#define BATCH 32
#define NTILE (16*8*32)       // 4096 tiles
#define NCTA  740             // 148 SMs x 5 resident CTAs: zero wave tail

typedef unsigned long long u64;

__device__ double       g_accum;   // zero at module load; reset by last CTA
__device__ unsigned int g_count;

// Gaussian window (ws=11, sigma=1.5), normalized — matches jnp float32 chain
__device__ __forceinline__ float gw(int k) {
    const float G[11] = {0.00102838f, 0.00759876f, 0.03600077f, 0.10936069f,
                         0.21300554f, 0.26601173f, 0.21300554f, 0.10936069f,
                         0.03600077f, 0.00759876f, 0.00102838f};
    return G[k];
}

// ---- f32x2 helpers: register-pair views, NO integer shifts ----
__device__ __forceinline__ u64 pk2(float lo, float hi) {
    u64 d; asm("mov.b64 %0, {%1, %2};" : "=l"(d) : "f"(lo), "f"(hi));
    return d;
}
__device__ __forceinline__ void upk2(u64 v, float& lo, float& hi) {
    asm("mov.b64 {%0, %1}, %2;" : "=f"(lo), "=f"(hi) : "l"(v));
}
__device__ __forceinline__ u64 fma2(u64 a, u64 b, u64 c) {
    u64 d; asm("fma.rn.f32x2 %0, %1, %2, %3;" : "=l"(d) : "l"(a), "l"(b), "l"(c));
    return d;
}
__device__ __forceinline__ u64 mul2(u64 a, u64 b) {
    u64 d; asm("mul.rn.f32x2 %0, %1, %2;" : "=l"(d) : "l"(a), "l"(b));
    return d;
}

// accumulate window element k (0..13) into the 4 packed h-accumulators
__device__ __forceinline__ void acc_tap(int k, float pv, float tv,
                                        u64* sm, u64* se) {
    float s = pv + tv;
    float d = pv - tv;
    u64 wk = pk2(s, d);
    u64 sq = mul2(wk, wk);                       // (s^2, d^2)
    #pragma unroll
    for (int i = 0; i < 4; i++) {
        int kk = k - i;
        if (kk >= 0 && kk < 11) {
            float g = gw(kk);
            u64 g2 = pk2(g, g);                  // compile-time constant pair
            sm[i] = fma2(g2, wk, sm[i]);
            se[i] = fma2(g2, sq, se[i]);
        }
    }
}

__global__ __launch_bounds__(256, 5)
void ssim_main_kernel(const float* __restrict__ pred,
                      const float* __restrict__ targ,
                      float* __restrict__ out)
{
    // packed horizontal blurs: ( (mu_s,mu_d) , (E_ss,E_dd) )
    __shared__ __align__(16) ulonglong2 hA[NRY * TILE_X];        // 37.9 KB
    __shared__ float red[8];

    const int tid = threadIdx.x;                 // 0..255
    const int tx  = tid & 31;
    const int ty  = tid >> 5;                    // 0..7
    float acc = 0.f;                             // per-thread, across tiles

    // ---- Persistent tile loop: 740 CTAs sweep 4096 tiles, zero wave tail
    for (int t = blockIdx.x; t < NTILE; t += NCTA) {
        const int bx = t & 15;
        const int by = (t >> 4) & 7;
        const int n  = t >> 7;
        const int x0 = bx * TILE_X - HALO;
        const int y0 = by * TILE_Y - HALO;
        const float* __restrict__ pbase = pred + (size_t)n * IMG * IMG;
        const float* __restrict__ tbase = targ + (size_t)n * IMG * IMG;
        const bool xint = (bx > 0) && (bx < 15);

        // ---- Phase 1+2 fused: horizontal blur of (s,d),(s^2,d^2) from gmem.
        // item (r,q) produces h-cols 4q..4q+3 of halo row r; window elems are
        // gmem x in [a0+3, a0+16] (a0 = x0+4q-3, a0+4 16B-aligned).
        for (int it = tid; it < NRY * 8; it += 256) {
            int r = it >> 3;
            int q = it & 7;
            int gy = y0 + r;
            bool yin = (unsigned)gy < IMG;

            u64 sm[4] = {0ull, 0ull, 0ull, 0ull};    // (mu_s_h, mu_d_h)
            u64 se[4] = {0ull, 0ull, 0ull, 0ull};    // (E_ss_h, E_dd_h)

            if (yin) {
                const float* __restrict__ prow = pbase + (size_t)gy * IMG;
                const float* __restrict__ trow = tbase + (size_t)gy * IMG;
                int a0 = x0 + 4 * q - 3;
                if (xint) {
                    // tap 0 scalar
                    float p3 = __ldg(prow + a0 + 3);
                    float t3 = __ldg(trow + a0 + 3);
                    // taps 1..4
                    float4 a = __ldg((const float4*)(prow + a0 + 4));
                    float4 b = __ldg((const float4*)(trow + a0 + 4));
                    acc_tap(0, p3, t3, sm, se);
                    acc_tap(1, a.x, b.x, sm, se);
                    acc_tap(2, a.y, b.y, sm, se);
                    acc_tap(3, a.z, b.z, sm, se);
                    acc_tap(4, a.w, b.w, sm, se);
                    // taps 5..8
                    a = __ldg((const float4*)(prow + a0 + 8));
                    b = __ldg((const float4*)(trow + a0 + 8));
                    acc_tap(5, a.x, b.x, sm, se);
                    acc_tap(6, a.y, b.y, sm, se);
                    acc_tap(7, a.z, b.z, sm, se);
                    acc_tap(8, a.w, b.w, sm, se);
                    // taps 9..12
                    a = __ldg((const float4*)(prow + a0 + 12));
                    b = __ldg((const float4*)(trow + a0 + 12));
                    // tap 13 scalar
                    float p16 = __ldg(prow + a0 + 16);
                    float t16 = __ldg(trow + a0 + 16);
                    acc_tap(9,  a.x, b.x, sm, se);
                    acc_tap(10, a.y, b.y, sm, se);
                    acc_tap(11, a.z, b.z, sm, se);
                    acc_tap(12, a.w, b.w, sm, se);
                    acc_tap(13, p16, t16, sm, se);
                } else {
                    #pragma unroll
                    for (int k = 0; k < 14; k++) {
                        int gx = a0 + k + 3;     // = x0 + 4q + k
                        bool in = (unsigned)gx < IMG;
                        float pv = in ? __ldg(prow + gx) : 0.f;
                        float tv = in ? __ldg(trow + gx) : 0.f;
                        acc_tap(k, pv, tv, sm, se);
                    }
                }
            }

            int ho = r * TILE_X + q * 4;
            #pragma unroll
            for (int i = 0; i < 4; i++)
                hA[ho + i] = make_ulonglong2(sm[i], se[i]);   // STS.128
        }
        __syncthreads();

        // ---- Phase 3: vertical blur + SSIM, 8 consecutive rows per thread
        const int rbase = ty * 8;                // output rows rbase..rbase+7

        u64 m[8], e[8];                          // (mu_s, mu_d), (E_ss, E_dd)
        #pragma unroll
        for (int i = 0; i < 8; i++) { m[i] = 0ull; e[i] = 0ull; }

        #pragma unroll
        for (int j = 0; j < 18; j++) {
            ulonglong2 v = hA[(rbase + j) * TILE_X + tx];   // LDS.128
            #pragma unroll
            for (int i = 0; i < 8; i++) {
                int k = j - i;
                if (k >= 0 && k < 11) {
                    float g = gw(k);
                    u64 g2 = pk2(g, g);
                    m[i] = fma2(g2, v.x, m[i]);
                    e[i] = fma2(g2, v.y, e[i]);
                }
            }
        }

        #pragma unroll
        for (int i = 0; i < 8; i++) {
            u64 msq = mul2(m[i], m[i]);          // (mu_s^2, mu_d^2)
            float ms2, md2, Ess, Edd;
            upk2(msq, ms2, md2);
            upk2(e[i], Ess, Edd);
            // 2*mu1mu2  = (ms2-md2)/2   mu1^2+mu2^2 = (ms2+md2)/2
            // 2*sigma12 = (Ess-Edd)/2 - 2mu1mu2
            // v1+v2     = (Ess+Edd)/2 - (mu1^2+mu2^2)
            const float C1 = 1e-4f;              // 0.01^2
            const float C2 = 9e-4f;              // 0.03^2
            float B = 0.5f * (ms2 - md2);
            float A = 0.5f * (ms2 + md2);
            float num = (B + C1) * (0.5f * (Ess - Edd) - B + C2);
            float den = (A + C1) * (0.5f * (Ess + Edd) - A + C2);
            acc += __fdividef(num, den);
        }
        __syncthreads();                         // hA write-after-read guard
    }

    // ---- Once per CTA: block reduce, last-CTA finalize
    #pragma unroll
    for (int o = 16; o > 0; o >>= 1)
        acc += __shfl_xor_sync(0xffffffffu, acc, o);
    if ((tid & 31) == 0) red[tid >> 5] = acc;
    __syncthreads();
    if (tid == 0) {
        float v = red[0] + red[1] + red[2] + red[3] +
                  red[4] + red[5] + red[6] + red[7];
        atomicAdd(&g_accum, (double)v);
        __threadfence();
        unsigned old = atomicAdd(&g_count, 1u);
        if (old == NCTA - 1) {
            __threadfence();
            double s = *((volatile double*)&g_accum);
            out[0] = (float)(1.0 - s / ((double)BATCH * IMG * IMG));
            g_accum = 0.0;                       // reset for next graph replay
            g_count = 0u;
        }
    }
}

extern "C" void kernel_launch(void* const* d_in, const int* in_sizes, int n_in,
                              void* d_out, int out_size)
{
    const float* pred = (const float*)d_in[0];
    const float* targ = (const float*)d_in[1];
    float* out = (float*)d_out;

    ssim_main_kernel<<<NCTA, 256>>>(pred, targ, out);
}

// round 12
// speedup vs baseline: 1.3267x; 1.2807x over previous
#include <cuda_runtime.h>

#define TILE_X 32
#define TILE_Y 64
#define HALO  5
#define NRY   74              // halo rows (TILE_Y + 2*HALO)
#define HSTRIDE 35            // hA row stride in ulonglong2: 32 cols + gap every 8
#define IMG   512
#define BATCH 32
#define NBLK  (16*8*32)       // 4096 blocks

typedef unsigned long long u64;

__device__ double       g_accum;   // zero at module load; reset by last block
__device__ unsigned int g_count;

// Gaussian window (ws=11, sigma=1.5), normalized — matches jnp float32 chain
__device__ __forceinline__ float gw(int k) {
    const float G[11] = {0.00102838f, 0.00759876f, 0.03600077f, 0.10936069f,
                         0.21300554f, 0.26601173f, 0.21300554f, 0.10936069f,
                         0.03600077f, 0.00759876f, 0.00102838f};
    return G[k];
}

// ---- f32x2 helpers: register-pair views, NO integer shifts ----
__device__ __forceinline__ u64 pk2(float lo, float hi) {
    u64 d; asm("mov.b64 %0, {%1, %2};" : "=l"(d) : "f"(lo), "f"(hi));
    return d;
}
__device__ __forceinline__ void upk2(u64 v, float& lo, float& hi) {
    asm("mov.b64 {%0, %1}, %2;" : "=f"(lo), "=f"(hi) : "l"(v));
}
__device__ __forceinline__ u64 fma2(u64 a, u64 b, u64 c) {
    u64 d; asm("fma.rn.f32x2 %0, %1, %2, %3;" : "=l"(d) : "l"(a), "l"(b), "l"(c));
    return d;
}
__device__ __forceinline__ u64 mul2(u64 a, u64 b) {
    u64 d; asm("mul.rn.f32x2 %0, %1, %2;" : "=l"(d) : "l"(a), "l"(b));
    return d;
}

// accumulate window element k (0..13) into the 4 packed h-accumulators
__device__ __forceinline__ void acc_tap(int k, float pv, float tv,
                                        u64* sm, u64* se) {
    float s = pv + tv;
    float d = pv - tv;
    u64 wk = pk2(s, d);
    u64 sq = mul2(wk, wk);                       // (s^2, d^2)
    #pragma unroll
    for (int i = 0; i < 4; i++) {
        int kk = k - i;
        if (kk >= 0 && kk < 11) {
            float g = gw(kk);
            u64 g2 = pk2(g, g);                  // compile-time constant pair
            sm[i] = fma2(g2, wk, sm[i]);
            se[i] = fma2(g2, sq, se[i]);
        }
    }
}

__global__ __launch_bounds__(256, 5)
void ssim_main_kernel(const float* __restrict__ pred,
                      const float* __restrict__ targ,
                      float* __restrict__ out)
{
    // packed horizontal blurs ( (mu_s,mu_d) , (E_ss,E_dd) ).
    // col c stored at idx c + (c>>3): one 16B gap per 8 cols -> conflict-free
    // STS (store-phase banks 16q+4(q>>1) all distinct) AND conflict-free LDS
    // (tx + (tx>>3) distinct mod 8 within each 8-lane phase).
    __shared__ __align__(16) ulonglong2 hA[NRY * HSTRIDE];      // 41.4 KB
    __shared__ float red[8];

    const int tid = threadIdx.x;                 // 0..255
    const int n  = blockIdx.z;
    const int x0 = blockIdx.x * TILE_X - HALO;
    const int y0 = blockIdx.y * TILE_Y - HALO;
    const float* __restrict__ pbase = pred + (size_t)n * IMG * IMG;
    const float* __restrict__ tbase = targ + (size_t)n * IMG * IMG;
    const bool xint = (blockIdx.x > 0) && (blockIdx.x < (IMG / TILE_X - 1));

    // ---- Phase 1+2 fused: horizontal blur of (s,d),(s^2,d^2) from gmem.
    // item (r,q) produces h-cols 4q..4q+3 of halo row r (identical to R9).
    for (int it = tid; it < NRY * 8; it += 256) {
        int r = it >> 3;
        int q = it & 7;
        int gy = y0 + r;
        bool yin = (unsigned)gy < IMG;

        u64 sm[4] = {0ull, 0ull, 0ull, 0ull};    // (mu_s_h, mu_d_h)
        u64 se[4] = {0ull, 0ull, 0ull, 0ull};    // (E_ss_h, E_dd_h)

        if (yin) {
            const float* __restrict__ prow = pbase + (size_t)gy * IMG;
            const float* __restrict__ trow = tbase + (size_t)gy * IMG;
            int a0 = x0 + 4 * q - 3;             // a0+4 is 16B-aligned
            if (xint) {
                // tap 0 scalar
                float p3 = __ldg(prow + a0 + 3);
                float t3 = __ldg(trow + a0 + 3);
                // taps 1..4
                float4 a = __ldg((const float4*)(prow + a0 + 4));
                float4 b = __ldg((const float4*)(trow + a0 + 4));
                acc_tap(0, p3, t3, sm, se);
                acc_tap(1, a.x, b.x, sm, se);
                acc_tap(2, a.y, b.y, sm, se);
                acc_tap(3, a.z, b.z, sm, se);
                acc_tap(4, a.w, b.w, sm, se);
                // taps 5..8
                a = __ldg((const float4*)(prow + a0 + 8));
                b = __ldg((const float4*)(trow + a0 + 8));
                acc_tap(5, a.x, b.x, sm, se);
                acc_tap(6, a.y, b.y, sm, se);
                acc_tap(7, a.z, b.z, sm, se);
                acc_tap(8, a.w, b.w, sm, se);
                // taps 9..12
                a = __ldg((const float4*)(prow + a0 + 12));
                b = __ldg((const float4*)(trow + a0 + 12));
                // tap 13 scalar
                float p16 = __ldg(prow + a0 + 16);
                float t16 = __ldg(trow + a0 + 16);
                acc_tap(9,  a.x, b.x, sm, se);
                acc_tap(10, a.y, b.y, sm, se);
                acc_tap(11, a.z, b.z, sm, se);
                acc_tap(12, a.w, b.w, sm, se);
                acc_tap(13, p16, t16, sm, se);
            } else {
                #pragma unroll
                for (int k = 0; k < 14; k++) {
                    int gx = a0 + k + 3;         // = x0 + 4q + k
                    bool in = (unsigned)gx < IMG;
                    float pv = in ? __ldg(prow + gx) : 0.f;
                    float tv = in ? __ldg(trow + gx) : 0.f;
                    acc_tap(k, pv, tv, sm, se);
                }
            }
        }

        // gap-padded index: cols 4q..4q+3 stay contiguous within an 8-block
        int ho = r * HSTRIDE + 4 * q + (q >> 1);
        #pragma unroll
        for (int i = 0; i < 4; i++)
            hA[ho + i] = make_ulonglong2(sm[i], se[i]);   // STS.128, conflict-free
    }
    __syncthreads();

    // ---- Phase 3: vertical blur + SSIM, 8 consecutive rows per thread
    const int tx = tid & 31;
    const int ty = tid >> 5;                     // 0..7
    const int rbase = ty * 8;                    // output rows rbase..rbase+7
    const int cidx = tx + (tx >> 3);             // gap-padded column index

    u64 m[8], e[8];                              // (mu_s, mu_d), (E_ss, E_dd)
    #pragma unroll
    for (int i = 0; i < 8; i++) { m[i] = 0ull; e[i] = 0ull; }

    #pragma unroll
    for (int j = 0; j < 18; j++) {
        ulonglong2 v = hA[(rbase + j) * HSTRIDE + cidx];   // LDS.128, conflict-free
        #pragma unroll
        for (int i = 0; i < 8; i++) {
            int k = j - i;
            if (k >= 0 && k < 11) {
                float g = gw(k);
                u64 g2 = pk2(g, g);
                m[i] = fma2(g2, v.x, m[i]);
                e[i] = fma2(g2, v.y, e[i]);
            }
        }
    }

    float acc = 0.f;
    #pragma unroll
    for (int i = 0; i < 8; i++) {
        u64 msq = mul2(m[i], m[i]);              // (mu_s^2, mu_d^2)
        float ms2, md2, Ess, Edd;
        upk2(msq, ms2, md2);
        upk2(e[i], Ess, Edd);
        // 2*mu1mu2  = (ms2-md2)/2   mu1^2+mu2^2 = (ms2+md2)/2
        // 2*sigma12 = (Ess-Edd)/2 - 2mu1mu2
        // v1+v2     = (Ess+Edd)/2 - (mu1^2+mu2^2)
        const float C1 = 1e-4f;                  // 0.01^2
        const float C2 = 9e-4f;                  // 0.03^2
        float B = 0.5f * (ms2 - md2);
        float A = 0.5f * (ms2 + md2);
        float num = (B + C1) * (0.5f * (Ess - Edd) - B + C2);
        float den = (A + C1) * (0.5f * (Ess + Edd) - A + C2);
        acc += __fdividef(num, den);
    }

    // ---- Phase 4: block reduce, last-block finalize (single kernel)
    #pragma unroll
    for (int o = 16; o > 0; o >>= 1)
        acc += __shfl_xor_sync(0xffffffffu, acc, o);
    if ((tid & 31) == 0) red[tid >> 5] = acc;
    __syncthreads();
    if (tid == 0) {
        float v = red[0] + red[1] + red[2] + red[3] +
                  red[4] + red[5] + red[6] + red[7];
        atomicAdd(&g_accum, (double)v);
        __threadfence();
        unsigned old = atomicAdd(&g_count, 1u);
        if (old == NBLK - 1) {
            __threadfence();
            double s = *((volatile double*)&g_accum);
            out[0] = (float)(1.0 - s / ((double)BATCH * IMG * IMG));
            g_accum = 0.0;                       // reset for next graph replay
            g_count = 0u;
        }
    }
}

extern "C" void kernel_launch(void* const* d_in, const int* in_sizes, int n_in,
                              void* d_out, int out_size)
{
    const float* pred = (const float*)d_in[0];
    const float* targ = (const float*)d_in[1];
    float* out = (float*)d_out;

    dim3 grid(IMG / TILE_X, IMG / TILE_Y, BATCH);    // 16 x 8 x 32
    ssim_main_kernel<<<grid, 256>>>(pred, targ, out);
}